// round 11
// baseline (speedup 1.0000x reference)
#include <cuda_runtime.h>
#include <cuda_fp16.h>
#include <math.h>
#include <stdint.h>

// Problem constants
#define ORDER   32
#define WHID    1024
#define OUTDIM  4096
#define SMAX    2048

// ---------------------------------------------------------------------------
// Scratch (device globals -- no allocations allowed)
// ---------------------------------------------------------------------------
__device__ __half g_A[SMAX * WHID];    // H1 (fp16, gemm2 input)
__device__ __half g_C[SMAX * WHID];    // H2 (fp16, gemm3 input)
__device__ __half g_W2h[WHID * WHID];
__device__ __half g_W3h[WHID * WHID];
__device__ float g_hsum[WHID];
__device__ float g_wsum[OUTDIM];
__device__ float g_bsum[1];

// ---------------------------------------------------------------------------
// PTX helpers
// ---------------------------------------------------------------------------
__device__ __forceinline__ uint32_t smem_u32(const void* p) {
    uint32_t a;
    asm("{ .reg .u64 t; cvta.to.shared.u64 t, %1; cvt.u32.u64 %0, t; }"
        : "=r"(a) : "l"(p));
    return a;
}
__device__ __forceinline__ void cp16(uint32_t saddr, const void* g) {
    asm volatile("cp.async.cg.shared.global [%0], [%1], 16;"
                 :: "r"(saddr), "l"(g) : "memory");
}
__device__ __forceinline__ void cp_commit() {
    asm volatile("cp.async.commit_group;" ::: "memory");
}
template <int N>
__device__ __forceinline__ void cp_wait() {
    asm volatile("cp.async.wait_group %0;" :: "n"(N) : "memory");
}
__device__ __forceinline__ void ldmx4(uint32_t* r, uint32_t addr) {
    asm volatile("ldmatrix.sync.aligned.m8n8.x4.shared.b16 {%0,%1,%2,%3}, [%4];"
                 : "=r"(r[0]), "=r"(r[1]), "=r"(r[2]), "=r"(r[3]) : "r"(addr));
}
__device__ __forceinline__ void mma16816h(float* d, const uint32_t* a,
                                          const uint32_t* b) {
    asm volatile(
        "mma.sync.aligned.m16n8k16.row.col.f32.f16.f16.f32 "
        "{%0,%1,%2,%3}, {%4,%5,%6,%7}, {%8,%9}, {%0,%1,%2,%3};"
        : "+f"(d[0]), "+f"(d[1]), "+f"(d[2]), "+f"(d[3])
        : "r"(a[0]), "r"(a[1]), "r"(a[2]), "r"(a[3]), "r"(b[0]), "r"(b[1]));
}

// Packed f32x2 ops (Blackwell FFMA2 path)
__device__ __forceinline__ uint64_t pack2(float lo, float hi) {
    uint64_t r;
    asm("mov.b64 %0, {%1, %2};" : "=l"(r) : "f"(lo), "f"(hi));
    return r;
}
__device__ __forceinline__ void unpack2(uint64_t v, float& lo, float& hi) {
    asm("mov.b64 {%0, %1}, %2;" : "=f"(lo), "=f"(hi) : "l"(v));
}
__device__ __forceinline__ uint64_t fma2(uint64_t a, uint64_t b, uint64_t c) {
    uint64_t r;
    asm("fma.rn.f32x2 %0, %1, %2, %3;" : "=l"(r) : "l"(a), "l"(b), "l"(c));
    return r;
}
__device__ __forceinline__ uint64_t add2(uint64_t a, uint64_t b) {
    uint64_t r;
    asm("add.rn.f32x2 %0, %1, %2;" : "=l"(r) : "l"(a), "l"(b));
    return r;
}

// ---------------------------------------------------------------------------
// GELU (tanh approximation, matches jax.nn.gelu)
// ---------------------------------------------------------------------------
__device__ __forceinline__ float gelu_f(float x) {
    const float k0 = 0.7978845608028654f;
    float x3 = x * x * x;
    float t = tanhf(k0 * (x + 0.044715f * x3));
    return 0.5f * x * (1.0f + t);
}

// ---------------------------------------------------------------------------
// prep: fused init + weight-convert + layer1 (all independent; blockIdx ranges)
// ---------------------------------------------------------------------------
__global__ __launch_bounds__(256)
void prep_kernel(const float* __restrict__ sources,
                 const float* __restrict__ W1, const float* __restrict__ b1,
                 const float* __restrict__ W2, const float* __restrict__ W3,
                 const float* __restrict__ Wb, const float* __restrict__ bb,
                 int S) {
    const int b = blockIdx.x;
    const int tid = threadIdx.x;
    const int M1 = WHID * WHID;

    if (b < 8192) {
        int idx = b * 256 + tid;
        if (idx < M1) g_W2h[idx] = __float2half_rn(W2[idx]);
        else          g_W3h[idx - M1] = __float2half_rn(W3[idx - M1]);
    } else if (b < 16384) {
        int idx = (b - 8192) * 256 + tid;
        int s = idx >> 10;
        int j = idx & (WHID - 1);
        float4 src = reinterpret_cast<const float4*>(sources)[s];
        float4 w   = reinterpret_cast<const float4*>(W1)[j];
        float acc = src.x * w.x + src.y * w.y + src.z * w.z + src.w * w.w + b1[j];
        g_A[idx] = __float2half_rn(gelu_f(acc));
    } else {
        for (int j = tid; j < WHID; j += 256) g_hsum[j] = 0.0f;
        float wb0 = Wb[0], wb1 = Wb[1], wb2 = Wb[2], wb3 = Wb[3];
        float acc = 0.0f;
        for (int s = tid; s < S; s += 256) {
            float4 v = reinterpret_cast<const float4*>(sources)[s];
            acc += v.x * wb0 + v.y * wb1 + v.z * wb2 + v.w * wb3;
        }
        __shared__ float red[256];
        red[tid] = acc;
        __syncthreads();
        for (int o = 128; o > 0; o >>= 1) {
            if (tid < o) red[tid] += red[tid + o];
            __syncthreads();
        }
        if (tid == 0) g_bsum[0] = red[0] + (float)S * bb[0];
    }
}

// ---------------------------------------------------------------------------
// mma.sync GEMM: C = gelu(A @ B^T + bias), fp16 x fp16 -> fp32 accum.
// CTA tile 128x128, BK=32, 512 threads / 16 warps, 3-stage cp.async pipeline.
// stage 0: out -> g_C (fp16);  stage 1: fused column sums -> g_hsum
// ---------------------------------------------------------------------------
__device__ __forceinline__ uint32_t sw32(uint32_t off) {
    return off ^ ((off >> 3) & 0x10);
}

__global__ __launch_bounds__(512, 1)
void mma_gemm(int stage, const float* __restrict__ bias) {
    __shared__ __align__(1024) char smem[3][2][8192];

    const __half* A = stage ? g_C : g_A;
    const __half* B = stage ? g_W3h : g_W2h;

    const int tid = threadIdx.x;
    const int wid = tid >> 5;
    const int lane = tid & 31;
    const int bm = blockIdx.y * 128;
    const int bn = blockIdx.x * 128;
    const int wm = wid & 3;
    const int wn = wid >> 2;

    const int lrow = tid >> 2;
    const int lsub = (tid >> 1) & 1;
    const int lc16 = tid & 1;
    const uint32_t loff = lsub * 4096 + sw32((uint32_t)(lrow * 32 + lc16 * 16));
    const int gk = lsub * 16 + lc16 * 8;
    const __half* srcA = A + (size_t)(bm + lrow) * WHID + gk;
    const __half* srcB = B + (size_t)(bn + lrow) * WHID + gk;

    uint32_t offA[2], offB[2];
#pragma unroll
    for (int i = 0; i < 2; i++) {
        int row = wm * 32 + i * 16 + (lane & 15);
        offA[i] = sw32((uint32_t)(row * 32 + (lane >> 4) * 16));
    }
#pragma unroll
    for (int j = 0; j < 2; j++) {
        int row = wn * 32 + j * 16 + (lane & 15);
        offB[j] = sw32((uint32_t)(row * 32 + (lane >> 4) * 16));
    }

    float acc[2][4][4];
#pragma unroll
    for (int i = 0; i < 2; i++)
#pragma unroll
        for (int j = 0; j < 4; j++)
#pragma unroll
            for (int q = 0; q < 4; q++) acc[i][j][q] = 0.0f;

#pragma unroll
    for (int p = 0; p < 2; p++) {
        cp16(smem_u32(&smem[p][0][0]) + loff, srcA + p * 32);
        cp16(smem_u32(&smem[p][1][0]) + loff, srcB + p * 32);
        cp_commit();
    }

    const int NIT = WHID / 32;   // 32
    for (int it = 0; it < NIT; it++) {
        const int st = it % 3;
        cp_wait<1>();
        __syncthreads();

        if (it + 2 < NIT) {
            const int ns = (it + 2) % 3;
            cp16(smem_u32(&smem[ns][0][0]) + loff, srcA + (it + 2) * 32);
            cp16(smem_u32(&smem[ns][1][0]) + loff, srcB + (it + 2) * 32);
        }
        cp_commit();

#pragma unroll
        for (int s = 0; s < 2; s++) {
            uint32_t ab = smem_u32(&smem[st][0][0]) + s * 4096;
            uint32_t bb = smem_u32(&smem[st][1][0]) + s * 4096;
            uint32_t a[2][4], b[2][4];
#pragma unroll
            for (int i = 0; i < 2; i++) ldmx4(a[i], ab + offA[i]);
#pragma unroll
            for (int j = 0; j < 2; j++) ldmx4(b[j], bb + offB[j]);

#pragma unroll
            for (int i = 0; i < 2; i++) {
#pragma unroll
                for (int jj = 0; jj < 4; jj++) {
                    uint32_t breg[2] = { b[jj >> 1][jj & 1], b[jj >> 1][(jj & 1) + 2] };
                    mma16816h(acc[i][jj], a[i], breg);
                }
            }
        }
    }

    // --- epilogue ---
    if (stage == 0) {
#pragma unroll
        for (int i = 0; i < 2; i++) {
            int r0 = bm + wm * 32 + i * 16 + (lane >> 2);
            int r1 = r0 + 8;
#pragma unroll
            for (int jj = 0; jj < 4; jj++) {
                int col = bn + wn * 32 + jj * 8 + (lane & 3) * 2;
                float b0 = bias[col], b1 = bias[col + 1];
                __half h0 = __float2half_rn(gelu_f(acc[i][jj][0] + b0));
                __half h1 = __float2half_rn(gelu_f(acc[i][jj][1] + b1));
                *reinterpret_cast<__half2*>(g_C + (size_t)r0 * WHID + col) =
                    __half2(h0, h1);
                h0 = __float2half_rn(gelu_f(acc[i][jj][2] + b0));
                h1 = __float2half_rn(gelu_f(acc[i][jj][3] + b1));
                *reinterpret_cast<__half2*>(g_C + (size_t)r1 * WHID + col) =
                    __half2(h0, h1);
            }
        }
    } else {
        float colacc[4][2];
#pragma unroll
        for (int jj = 0; jj < 4; jj++) { colacc[jj][0] = 0.0f; colacc[jj][1] = 0.0f; }

#pragma unroll
        for (int i = 0; i < 2; i++) {
#pragma unroll
            for (int jj = 0; jj < 4; jj++) {
                int col = bn + wn * 32 + jj * 8 + (lane & 3) * 2;
                float b0 = bias[col], b1 = bias[col + 1];
                colacc[jj][0] += gelu_f(acc[i][jj][0] + b0) + gelu_f(acc[i][jj][2] + b0);
                colacc[jj][1] += gelu_f(acc[i][jj][1] + b1) + gelu_f(acc[i][jj][3] + b1);
            }
        }
#pragma unroll
        for (int o = 16; o >= 4; o >>= 1) {
#pragma unroll
            for (int jj = 0; jj < 4; jj++) {
                colacc[jj][0] += __shfl_xor_sync(0xffffffffu, colacc[jj][0], o);
                colacc[jj][1] += __shfl_xor_sync(0xffffffffu, colacc[jj][1], o);
            }
        }
        if (lane < 4) {
#pragma unroll
            for (int jj = 0; jj < 4; jj++) {
                int col = bn + wn * 32 + jj * 8 + lane * 2;
                atomicAdd(&g_hsum[col],     colacc[jj][0]);
                atomicAdd(&g_hsum[col + 1], colacc[jj][1]);
            }
        }
    }
}

// ---------------------------------------------------------------------------
// wsum[k] = hsum . W4[k,:] + S*b4[k]
// One warp per output row; lane loads 8 independent float4 -> MLP~8,
// bandwidth-bound (16MB of W4).
// ---------------------------------------------------------------------------
__global__ __launch_bounds__(256)
void wsum_kernel(const float* __restrict__ W4,
                 const float* __restrict__ b4, float Sf) {
    int k = blockIdx.x * 8 + (threadIdx.x >> 5);
    int lane = threadIdx.x & 31;
    const float4* row = reinterpret_cast<const float4*>(W4 + (size_t)k * WHID);
    const float4* hs  = reinterpret_cast<const float4*>(g_hsum);

    float4 w[8], h[8];
#pragma unroll
    for (int q = 0; q < 8; q++) w[q] = row[lane + q * 32];
#pragma unroll
    for (int q = 0; q < 8; q++) h[q] = hs[lane + q * 32];

    float acc = 0.0f;
#pragma unroll
    for (int q = 0; q < 8; q++) {
        acc += w[q].x * h[q].x + w[q].y * h[q].y +
               w[q].z * h[q].z + w[q].w * h[q].w;
    }
#pragma unroll
    for (int o = 16; o > 0; o >>= 1) acc += __shfl_xor_sync(0xffffffffu, acc, o);
    if (lane == 0) g_wsum[k] = acc + Sf * b4[k];
}

// ---------------------------------------------------------------------------
// Fourier: out[n] = bsum + u(x)^T K v(y), packed f32x2 inner product
// ---------------------------------------------------------------------------
__global__ __launch_bounds__(256)
void fourier_kernel(const float* __restrict__ r, float* __restrict__ out, int N) {
    __shared__ float Ks[64 * 64];
    for (int t = threadIdx.x; t < 64 * 64; t += 256) {
        int a = t >> 6, b = t & 63;
        int i = a & 31, j = b & 31;
        int c = (a < 32) ? ((b < 32) ? 0 : 2) : ((b < 32) ? 3 : 1);
        Ks[t] = g_wsum[c * 1024 + i * 32 + j];
    }
    __syncthreads();

    int n = blockIdx.x * 256 + threadIdx.x;
    if (n >= N) return;

    float x = r[2 * n + 0];
    float y = r[2 * n + 1];
    const float w1 = 0.6283185307179586f;   // 2*pi/10

    float sx1, cx1, sy1, cy1;
    sincosf(w1 * x, &sx1, &cx1);
    sincosf(w1 * y, &sy1, &cy1);

    float v[64];
    {
        float cc = cy1, ss = sy1;
        v[0] = cc; v[32] = ss;
#pragma unroll
        for (int k = 1; k < 32; k++) {
            float cn = cc * cy1 - ss * sy1;
            float sn = ss * cy1 + cc * sy1;
            cc = cn; ss = sn;
            v[k] = cc; v[32 + k] = ss;
        }
    }
    uint64_t v2[32];
#pragma unroll
    for (int j = 0; j < 32; j++) v2[j] = pack2(v[2 * j], v[2 * j + 1]);

    uint64_t resc = 0ull, ress = 0ull;
    float cxa = cx1, sxa = sx1;
#pragma unroll 1
    for (int k = 0; k < 32; k++) {
        const ulonglong2* rc = (const ulonglong2*)&Ks[k * 64];
        const ulonglong2* rs = (const ulonglong2*)&Ks[(32 + k) * 64];
        uint64_t a0 = 0ull, a1 = 0ull, b0 = 0ull, b1 = 0ull;
#pragma unroll
        for (int q = 0; q < 16; q++) {
            ulonglong2 kc = rc[q];
            ulonglong2 ks = rs[q];
            a0 = fma2(kc.x, v2[2 * q],     a0);
            a1 = fma2(kc.y, v2[2 * q + 1], a1);
            b0 = fma2(ks.x, v2[2 * q],     b0);
            b1 = fma2(ks.y, v2[2 * q + 1], b1);
        }
        resc = fma2(pack2(cxa, cxa), add2(a0, a1), resc);
        ress = fma2(pack2(sxa, sxa), add2(b0, b1), ress);

        float cn = cxa * cx1 - sxa * sx1;
        float sn = sxa * cx1 + cxa * sx1;
        cxa = cn; sxa = sn;
    }

    float r0, r1, r2, r3;
    unpack2(resc, r0, r1);
    unpack2(ress, r2, r3);
    out[n] = g_bsum[0] + ((r0 + r1) + (r2 + r3));
}

// ---------------------------------------------------------------------------
// kernel_launch
// ---------------------------------------------------------------------------
extern "C" void kernel_launch(void* const* d_in, const int* in_sizes, int n_in,
                              void* d_out, int out_size) {
    const float* sources = (const float*)d_in[0];
    const float* r       = (const float*)d_in[1];
    const float* W1      = (const float*)d_in[2];
    const float* b1      = (const float*)d_in[3];
    const float* W2      = (const float*)d_in[4];
    const float* b2      = (const float*)d_in[5];
    const float* W3      = (const float*)d_in[6];
    const float* b3      = (const float*)d_in[7];
    const float* W4      = (const float*)d_in[8];
    const float* b4      = (const float*)d_in[9];
    const float* Wb      = (const float*)d_in[10];
    const float* bb      = (const float*)d_in[11];
    float* out = (float*)d_out;

    const int S = in_sizes[0] / 4;
    const int N = in_sizes[1] / 2;

    // 1) fused prep: weight fp16 convert + layer1 + init
    prep_kernel<<<16385, 256>>>(sources, W1, b1, W2, W3, Wb, bb, S);

    // 2) tensor-core GELU-GEMMs (layers 2 and 3; layer-3 fuses column sum)
    {
        dim3 grid(WHID / 128, S / 128);
        mma_gemm<<<grid, 512>>>(0, b2);   // H1 -> H2 (fp16)
        mma_gemm<<<grid, 512>>>(1, b3);   // H2 -> hsum (fused column sum)
    }

    // 3) wsum = hsum @ W4^T + S*b4
    wsum_kernel<<<OUTDIM / 8, 256>>>(W4, b4, (float)S);

    // 4) fourier expansion
    fourier_kernel<<<(N + 255) / 256, 256>>>(r, out, N);
}

// round 12
// speedup vs baseline: 1.1937x; 1.1937x over previous
#include <cuda_runtime.h>
#include <cuda_fp16.h>
#include <math.h>
#include <stdint.h>

// Problem constants
#define ORDER   32
#define WHID    1024
#define OUTDIM  4096
#define SMAX    2048

// ---------------------------------------------------------------------------
// Scratch (device globals -- no allocations allowed)
// ---------------------------------------------------------------------------
__device__ __half g_A[SMAX * WHID];    // H1 (fp16, gemm2 input)
__device__ __half g_C[SMAX * WHID];    // H2 (fp16, gemm3 input)
__device__ __half g_W2h[WHID * WHID];
__device__ __half g_W3h[WHID * WHID];
__device__ float g_hsum[WHID];
__device__ float g_wsum[OUTDIM];
__device__ float g_bsum[1];

// ---------------------------------------------------------------------------
// PTX helpers
// ---------------------------------------------------------------------------
__device__ __forceinline__ uint32_t smem_u32(const void* p) {
    uint32_t a;
    asm("{ .reg .u64 t; cvta.to.shared.u64 t, %1; cvt.u32.u64 %0, t; }"
        : "=r"(a) : "l"(p));
    return a;
}
__device__ __forceinline__ void cp16(uint32_t saddr, const void* g) {
    asm volatile("cp.async.cg.shared.global [%0], [%1], 16;"
                 :: "r"(saddr), "l"(g) : "memory");
}
__device__ __forceinline__ void cp_commit() {
    asm volatile("cp.async.commit_group;" ::: "memory");
}
template <int N>
__device__ __forceinline__ void cp_wait() {
    asm volatile("cp.async.wait_group %0;" :: "n"(N) : "memory");
}
__device__ __forceinline__ void ldmx4(uint32_t* r, uint32_t addr) {
    asm volatile("ldmatrix.sync.aligned.m8n8.x4.shared.b16 {%0,%1,%2,%3}, [%4];"
                 : "=r"(r[0]), "=r"(r[1]), "=r"(r[2]), "=r"(r[3]) : "r"(addr));
}
__device__ __forceinline__ void mma16816h(float* d, const uint32_t* a,
                                          const uint32_t* b) {
    asm volatile(
        "mma.sync.aligned.m16n8k16.row.col.f32.f16.f16.f32 "
        "{%0,%1,%2,%3}, {%4,%5,%6,%7}, {%8,%9}, {%0,%1,%2,%3};"
        : "+f"(d[0]), "+f"(d[1]), "+f"(d[2]), "+f"(d[3])
        : "r"(a[0]), "r"(a[1]), "r"(a[2]), "r"(a[3]), "r"(b[0]), "r"(b[1]));
}

// ---------------------------------------------------------------------------
// GELU (tanh approximation, matches jax.nn.gelu)
// ---------------------------------------------------------------------------
__device__ __forceinline__ float gelu_f(float x) {
    const float k0 = 0.7978845608028654f;
    float x3 = x * x * x;
    float t = tanhf(k0 * (x + 0.044715f * x3));
    return 0.5f * x * (1.0f + t);
}

// ---------------------------------------------------------------------------
// prep: fused init + weight-convert + layer1 (all independent; blockIdx ranges)
// ---------------------------------------------------------------------------
__global__ __launch_bounds__(256)
void prep_kernel(const float* __restrict__ sources,
                 const float* __restrict__ W1, const float* __restrict__ b1,
                 const float* __restrict__ W2, const float* __restrict__ W3,
                 const float* __restrict__ Wb, const float* __restrict__ bb,
                 int S) {
    const int b = blockIdx.x;
    const int tid = threadIdx.x;
    const int M1 = WHID * WHID;

    if (b < 8192) {
        int idx = b * 256 + tid;
        if (idx < M1) g_W2h[idx] = __float2half_rn(W2[idx]);
        else          g_W3h[idx - M1] = __float2half_rn(W3[idx - M1]);
    } else if (b < 16384) {
        int idx = (b - 8192) * 256 + tid;
        int s = idx >> 10;
        int j = idx & (WHID - 1);
        float4 src = reinterpret_cast<const float4*>(sources)[s];
        float4 w   = reinterpret_cast<const float4*>(W1)[j];
        float acc = src.x * w.x + src.y * w.y + src.z * w.z + src.w * w.w + b1[j];
        g_A[idx] = __float2half_rn(gelu_f(acc));
    } else {
        for (int j = tid; j < WHID; j += 256) g_hsum[j] = 0.0f;
        float wb0 = Wb[0], wb1 = Wb[1], wb2 = Wb[2], wb3 = Wb[3];
        float acc = 0.0f;
        for (int s = tid; s < S; s += 256) {
            float4 v = reinterpret_cast<const float4*>(sources)[s];
            acc += v.x * wb0 + v.y * wb1 + v.z * wb2 + v.w * wb3;
        }
        __shared__ float red[256];
        red[tid] = acc;
        __syncthreads();
        for (int o = 128; o > 0; o >>= 1) {
            if (tid < o) red[tid] += red[tid + o];
            __syncthreads();
        }
        if (tid == 0) g_bsum[0] = red[0] + (float)S * bb[0];
    }
}

// ---------------------------------------------------------------------------
// mma.sync GEMM: C = gelu(A @ B^T + bias), fp16 x fp16 -> fp32 accum.
// ---------------------------------------------------------------------------
__device__ __forceinline__ uint32_t sw32(uint32_t off) {
    return off ^ ((off >> 3) & 0x10);
}

__global__ __launch_bounds__(512, 1)
void mma_gemm(int stage, const float* __restrict__ bias) {
    __shared__ __align__(1024) char smem[3][2][8192];

    const __half* A = stage ? g_C : g_A;
    const __half* B = stage ? g_W3h : g_W2h;

    const int tid = threadIdx.x;
    const int wid = tid >> 5;
    const int lane = tid & 31;
    const int bm = blockIdx.y * 128;
    const int bn = blockIdx.x * 128;
    const int wm = wid & 3;
    const int wn = wid >> 2;

    const int lrow = tid >> 2;
    const int lsub = (tid >> 1) & 1;
    const int lc16 = tid & 1;
    const uint32_t loff = lsub * 4096 + sw32((uint32_t)(lrow * 32 + lc16 * 16));
    const int gk = lsub * 16 + lc16 * 8;
    const __half* srcA = A + (size_t)(bm + lrow) * WHID + gk;
    const __half* srcB = B + (size_t)(bn + lrow) * WHID + gk;

    uint32_t offA[2], offB[2];
#pragma unroll
    for (int i = 0; i < 2; i++) {
        int row = wm * 32 + i * 16 + (lane & 15);
        offA[i] = sw32((uint32_t)(row * 32 + (lane >> 4) * 16));
    }
#pragma unroll
    for (int j = 0; j < 2; j++) {
        int row = wn * 32 + j * 16 + (lane & 15);
        offB[j] = sw32((uint32_t)(row * 32 + (lane >> 4) * 16));
    }

    float acc[2][4][4];
#pragma unroll
    for (int i = 0; i < 2; i++)
#pragma unroll
        for (int j = 0; j < 4; j++)
#pragma unroll
            for (int q = 0; q < 4; q++) acc[i][j][q] = 0.0f;

#pragma unroll
    for (int p = 0; p < 2; p++) {
        cp16(smem_u32(&smem[p][0][0]) + loff, srcA + p * 32);
        cp16(smem_u32(&smem[p][1][0]) + loff, srcB + p * 32);
        cp_commit();
    }

    const int NIT = WHID / 32;   // 32
    for (int it = 0; it < NIT; it++) {
        const int st = it % 3;
        cp_wait<1>();
        __syncthreads();

        if (it + 2 < NIT) {
            const int ns = (it + 2) % 3;
            cp16(smem_u32(&smem[ns][0][0]) + loff, srcA + (it + 2) * 32);
            cp16(smem_u32(&smem[ns][1][0]) + loff, srcB + (it + 2) * 32);
        }
        cp_commit();

#pragma unroll
        for (int s = 0; s < 2; s++) {
            uint32_t ab = smem_u32(&smem[st][0][0]) + s * 4096;
            uint32_t bb = smem_u32(&smem[st][1][0]) + s * 4096;
            uint32_t a[2][4], b[2][4];
#pragma unroll
            for (int i = 0; i < 2; i++) ldmx4(a[i], ab + offA[i]);
#pragma unroll
            for (int j = 0; j < 2; j++) ldmx4(b[j], bb + offB[j]);

#pragma unroll
            for (int i = 0; i < 2; i++) {
#pragma unroll
                for (int jj = 0; jj < 4; jj++) {
                    uint32_t breg[2] = { b[jj >> 1][jj & 1], b[jj >> 1][(jj & 1) + 2] };
                    mma16816h(acc[i][jj], a[i], breg);
                }
            }
        }
    }

    // --- epilogue ---
    if (stage == 0) {
#pragma unroll
        for (int i = 0; i < 2; i++) {
            int r0 = bm + wm * 32 + i * 16 + (lane >> 2);
            int r1 = r0 + 8;
#pragma unroll
            for (int jj = 0; jj < 4; jj++) {
                int col = bn + wn * 32 + jj * 8 + (lane & 3) * 2;
                float b0 = bias[col], b1 = bias[col + 1];
                __half h0 = __float2half_rn(gelu_f(acc[i][jj][0] + b0));
                __half h1 = __float2half_rn(gelu_f(acc[i][jj][1] + b1));
                *reinterpret_cast<__half2*>(g_C + (size_t)r0 * WHID + col) =
                    __half2(h0, h1);
                h0 = __float2half_rn(gelu_f(acc[i][jj][2] + b0));
                h1 = __float2half_rn(gelu_f(acc[i][jj][3] + b1));
                *reinterpret_cast<__half2*>(g_C + (size_t)r1 * WHID + col) =
                    __half2(h0, h1);
            }
        }
    } else {
        float colacc[4][2];
#pragma unroll
        for (int jj = 0; jj < 4; jj++) { colacc[jj][0] = 0.0f; colacc[jj][1] = 0.0f; }

#pragma unroll
        for (int i = 0; i < 2; i++) {
#pragma unroll
            for (int jj = 0; jj < 4; jj++) {
                int col = bn + wn * 32 + jj * 8 + (lane & 3) * 2;
                float b0 = bias[col], b1 = bias[col + 1];
                colacc[jj][0] += gelu_f(acc[i][jj][0] + b0) + gelu_f(acc[i][jj][2] + b0);
                colacc[jj][1] += gelu_f(acc[i][jj][1] + b1) + gelu_f(acc[i][jj][3] + b1);
            }
        }
#pragma unroll
        for (int o = 16; o >= 4; o >>= 1) {
#pragma unroll
            for (int jj = 0; jj < 4; jj++) {
                colacc[jj][0] += __shfl_xor_sync(0xffffffffu, colacc[jj][0], o);
                colacc[jj][1] += __shfl_xor_sync(0xffffffffu, colacc[jj][1], o);
            }
        }
        if (lane < 4) {
#pragma unroll
            for (int jj = 0; jj < 4; jj++) {
                int col = bn + wn * 32 + jj * 8 + lane * 2;
                atomicAdd(&g_hsum[col],     colacc[jj][0]);
                atomicAdd(&g_hsum[col + 1], colacc[jj][1]);
            }
        }
    }
}

// ---------------------------------------------------------------------------
// wsum[k] = hsum . W4[k,:] + S*b4[k]  (vectorized, MLP~8, BW-bound)
// ---------------------------------------------------------------------------
__global__ __launch_bounds__(256)
void wsum_kernel(const float* __restrict__ W4,
                 const float* __restrict__ b4, float Sf) {
    int k = blockIdx.x * 8 + (threadIdx.x >> 5);
    int lane = threadIdx.x & 31;
    const float4* row = reinterpret_cast<const float4*>(W4 + (size_t)k * WHID);
    const float4* hs  = reinterpret_cast<const float4*>(g_hsum);

    float4 w[8], h[8];
#pragma unroll
    for (int q = 0; q < 8; q++) w[q] = row[lane + q * 32];
#pragma unroll
    for (int q = 0; q < 8; q++) h[q] = hs[lane + q * 32];

    float acc = 0.0f;
#pragma unroll
    for (int q = 0; q < 8; q++) {
        acc += w[q].x * h[q].x + w[q].y * h[q].y +
               w[q].z * h[q].z + w[q].w * h[q].w;
    }
#pragma unroll
    for (int o = 16; o > 0; o >>= 1) acc += __shfl_xor_sync(0xffffffffu, acc, o);
    if (lane == 0) g_wsum[k] = acc + Sf * b4[k];
}

// ---------------------------------------------------------------------------
// Fourier via tensor cores.
// Per CTA (256 points, 256 threads / 8 warps):
//   phase 1: build K (fp16 hi/lo, A-operand layout), V (fp16, B-operand
//            layout), U (fp32, padded stride 260) in smem
//   phase 2: T = (Khi + Klo) @ V  via mma.sync   (T in accumulators)
//   phase 3: out[n] = bsum + sum_a U[a,n] * T[a,n]  (shfl + smem atomics)
// smem: K 16KB | V 32KB | U 66.56KB | outbuf 1KB  = ~115.6KB (dynamic)
// ---------------------------------------------------------------------------
#define F_OFF_K   0
#define F_OFF_V   16384
#define F_OFF_U   49152
#define F_OFF_OUT 115712
#define F_SMEM    116768

__global__ __launch_bounds__(256, 1)
void fourier_kernel(const float* __restrict__ r, float* __restrict__ out, int N) {
    extern __shared__ __align__(16) char fs[];
    const uint32_t sbase = smem_u32(fs);
    float* Uf = reinterpret_cast<float*>(fs + F_OFF_U);
    float* outb = reinterpret_cast<float*>(fs + F_OFF_OUT);

    const int tid = threadIdx.x;
    const int wid = tid >> 5;
    const int lane = tid & 31;
    const int wm = wid & 3;       // 0..3 -> 16 a-rows each
    const int wn = wid >> 2;      // 0..1 -> 128 points each

    outb[tid] = 0.0f;

    // --- phase 0: build K hi/lo in A-operand layout ---
    for (int t = tid; t < 4096; t += 256) {
        int a = t >> 6, b = t & 63;
        int i = a & 31, j = b & 31;
        int c = (a < 32) ? ((b < 32) ? 0 : 2) : ((b < 32) ? 3 : 1);
        float w = g_wsum[c * 1024 + i * 32 + j];
        __half hi = __float2half_rn(w);
        __half lo = __float2half_rn(w - __half2float(hi));
        int ks = b >> 4;
        int b16 = b & 15;
        uint32_t off = ks * 2048 + sw32((uint32_t)(a * 32 + (b16 >> 3) * 16)) +
                       (b16 & 7) * 2;
        *reinterpret_cast<__half*>(fs + F_OFF_K + off) = hi;
        *reinterpret_cast<__half*>(fs + F_OFF_K + 8192 + off) = lo;
    }

    // --- phase 1: per-point u (fp32->smem) and v (fp16->smem, B layout) ---
    {
        int n = blockIdx.x * 256 + tid;
        float x = 0.0f, y = 0.0f;
        if (n < N) { x = r[2 * n + 0]; y = r[2 * n + 1]; }
        const float w1 = 0.6283185307179586f;   // 2*pi/10

        float sx1, cx1, sy1, cy1;
        sincosf(w1 * x, &sx1, &cx1);
        sincosf(w1 * y, &sy1, &cy1);

        float v[64], u[64];
        {
            float cc = cy1, ss = sy1;
            v[0] = cc; v[32] = ss;
#pragma unroll
            for (int k = 1; k < 32; k++) {
                float cn = cc * cy1 - ss * sy1;
                float sn = ss * cy1 + cc * sy1;
                cc = cn; ss = sn;
                v[k] = cc; v[32 + k] = ss;
            }
        }
        {
            float cc = cx1, ss = sx1;
            u[0] = cc; u[32] = ss;
#pragma unroll
            for (int k = 1; k < 32; k++) {
                float cn = cc * cx1 - ss * sx1;
                float sn = ss * cx1 + cc * sx1;
                cc = cn; ss = sn;
                u[k] = cc; u[32 + k] = ss;
            }
        }

        // V store: B-operand layout [ksub][row=tid][c16]
#pragma unroll
        for (int ks = 0; ks < 4; ks++) {
#pragma unroll
            for (int c16 = 0; c16 < 2; c16++) {
                __half hv[8];
#pragma unroll
                for (int e = 0; e < 8; e++)
                    hv[e] = __float2half_rn(v[ks * 16 + c16 * 8 + e]);
                uint32_t off = F_OFF_V + ks * 8192 +
                               sw32((uint32_t)(tid * 32 + c16 * 16));
                *reinterpret_cast<uint4*>(fs + off) =
                    *reinterpret_cast<uint4*>(hv);
            }
        }
        // U store: fp32, stride 260 (bank-conflict-free column reads)
#pragma unroll
        for (int a = 0; a < 64; a++) Uf[a * 260 + tid] = u[a];
    }
    __syncthreads();

    // --- phase 2: T = (Khi + Klo) @ V ---
    const uint32_t offA = sw32((uint32_t)((wm * 16 + (lane & 15)) * 32 +
                                          (lane >> 4) * 16));
    uint32_t offB[8];
#pragma unroll
    for (int p = 0; p < 8; p++) {
        int row = wn * 128 + p * 16 + (lane & 15);
        offB[p] = sw32((uint32_t)(row * 32 + (lane >> 4) * 16));
    }

    float acc[16][4];
#pragma unroll
    for (int nt = 0; nt < 16; nt++)
#pragma unroll
        for (int q = 0; q < 4; q++) acc[nt][q] = 0.0f;

#pragma unroll
    for (int ks = 0; ks < 4; ks++) {
        uint32_t ah[4], al[4];
        ldmx4(ah, sbase + F_OFF_K + ks * 2048 + offA);
        ldmx4(al, sbase + F_OFF_K + 8192 + ks * 2048 + offA);
#pragma unroll
        for (int p = 0; p < 8; p++) {
            uint32_t bf[4];
            ldmx4(bf, sbase + F_OFF_V + ks * 8192 + offB[p]);
#pragma unroll
            for (int h = 0; h < 2; h++) {
                uint32_t breg[2] = { bf[h], bf[h + 2] };
                mma16816h(acc[p * 2 + h], ah, breg);
                mma16816h(acc[p * 2 + h], al, breg);
            }
        }
    }

    // --- phase 3: out[n] = sum_a U[a,n] * T[a,n] ---
    {
        int r0 = wm * 16 + (lane >> 2);
        int r1 = r0 + 8;
#pragma unroll
        for (int nt = 0; nt < 16; nt++) {
            int c0 = wn * 128 + nt * 8 + (lane & 3) * 2;
            float p0 = acc[nt][0] * Uf[r0 * 260 + c0] +
                       acc[nt][2] * Uf[r1 * 260 + c0];
            float p1 = acc[nt][1] * Uf[r0 * 260 + c0 + 1] +
                       acc[nt][3] * Uf[r1 * 260 + c0 + 1];
            p0 += __shfl_xor_sync(0xffffffffu, p0, 16);
            p1 += __shfl_xor_sync(0xffffffffu, p1, 16);
            p0 += __shfl_xor_sync(0xffffffffu, p0, 8);
            p1 += __shfl_xor_sync(0xffffffffu, p1, 8);
            p0 += __shfl_xor_sync(0xffffffffu, p0, 4);
            p1 += __shfl_xor_sync(0xffffffffu, p1, 4);
            if (lane < 4) {
                atomicAdd(&outb[c0], p0);
                atomicAdd(&outb[c0 + 1], p1);
            }
        }
    }
    __syncthreads();

    int n = blockIdx.x * 256 + tid;
    if (n < N) out[n] = g_bsum[0] + outb[tid];
}

// ---------------------------------------------------------------------------
// kernel_launch
// ---------------------------------------------------------------------------
extern "C" void kernel_launch(void* const* d_in, const int* in_sizes, int n_in,
                              void* d_out, int out_size) {
    const float* sources = (const float*)d_in[0];
    const float* r       = (const float*)d_in[1];
    const float* W1      = (const float*)d_in[2];
    const float* b1      = (const float*)d_in[3];
    const float* W2      = (const float*)d_in[4];
    const float* b2      = (const float*)d_in[5];
    const float* W3      = (const float*)d_in[6];
    const float* b3      = (const float*)d_in[7];
    const float* W4      = (const float*)d_in[8];
    const float* b4      = (const float*)d_in[9];
    const float* Wb      = (const float*)d_in[10];
    const float* bb      = (const float*)d_in[11];
    float* out = (float*)d_out;

    const int S = in_sizes[0] / 4;
    const int N = in_sizes[1] / 2;

    // allow >48KB dynamic smem for the fourier kernel (idempotent host call)
    cudaFuncSetAttribute(fourier_kernel,
                         cudaFuncAttributeMaxDynamicSharedMemorySize, F_SMEM);

    // 1) fused prep: weight fp16 convert + layer1 + init
    prep_kernel<<<16385, 256>>>(sources, W1, b1, W2, W3, Wb, bb, S);

    // 2) tensor-core GELU-GEMMs (layers 2 and 3; layer-3 fuses column sum)
    {
        dim3 grid(WHID / 128, S / 128);
        mma_gemm<<<grid, 512>>>(0, b2);   // H1 -> H2 (fp16)
        mma_gemm<<<grid, 512>>>(1, b3);   // H2 -> hsum (fused column sum)
    }

    // 3) wsum = hsum @ W4^T + S*b4
    wsum_kernel<<<OUTDIM / 8, 256>>>(W4, b4, (float)S);

    // 4) fourier expansion (tensor-core bilinear form)
    fourier_kernel<<<(N + 255) / 256, 256, F_SMEM>>>(r, out, N);
}